// round 11
// baseline (speedup 1.0000x reference)
#include <cuda_runtime.h>
#include <math.h>

// ---------------- problem constants ----------------
#define BATCH   2
#define SEQ     2048
#define DIM     1024
#define HEADS   16
#define DHEAD   64
#define LATENT  256
#define MROWS   (BATCH * SEQ)          // 4096
#define SCALE   0.125f                 // DHEAD^-0.5

// ---------------- scratch (device globals; no allocation APIs) ----------------
__device__ float g_q  [MROWS * DIM];     // 16 MB
__device__ float g_lat[MROWS * LATENT];  //  4 MB
__device__ float g_k  [MROWS * DIM];     // 16 MB
__device__ float g_v  [MROWS * DIM];     // 16 MB
__device__ float g_ao [MROWS * DIM];     // 16 MB

// packed fp32x2 ops (Blackwell)
#define FMA2(acc, a, b) \
    asm("fma.rn.f32x2 %0, %1, %2, %0;" : "+l"(acc) : "l"(a), "l"(b))
#define MUL2(acc, s) \
    asm("mul.rn.f32x2 %0, %0, %1;" : "+l"(acc) : "l"(s))
#define UNPK(lo, hi, v) \
    asm("mov.b64 {%0, %1}, %2;" : "=f"(lo), "=f"(hi) : "l"(v))
#define PACK(v, lo, hi) \
    asm("mov.b64 %0, {%1, %2};" : "=l"(v) : "f"(lo), "f"(hi))

// ============================================================================
// SGEMM + bias via fma.rn.f32x2:  C[M,N] = A[M,K] @ B[K,N] + bias[N]
// 128x128 tile, BK=8, double-buffered, 256 threads, 8x8 microtile.
// A tile stored DUPLICATED in smem so ulonglong2 LDS yields {a,a} pairs.
// (measured round 3: ~148 TF/s fp32 effective on Q-proj)
// ============================================================================
__global__ __launch_bounds__(256, 2)
void gemm_bias_kernel(const float* __restrict__ A,
                      const float* __restrict__ B,
                      const float* __restrict__ bias,
                      float* __restrict__ C,
                      int M, int N, int K)
{
    __shared__ __align__(16) float sA2[2][8][260];
    __shared__ __align__(16) float sB [2][8][128];

    const int t  = threadIdx.x;
    const int tx = t & 15;
    const int ty = t >> 4;
    const int m0 = blockIdx.y * 128;
    const int n0 = blockIdx.x * 128;

    const int arow = t >> 1;
    const int acol = (t & 1) * 4;
    const int brow = t >> 5;
    const int bcol = (t & 31) * 4;

    const float* Aptr = A + (size_t)(m0 + arow) * K + acol;
    const float* Bptr = B + (size_t)brow * N + n0 + bcol;

    unsigned long long acc2[8][4];
#pragma unroll
    for (int j = 0; j < 8; j++)
#pragma unroll
        for (int i = 0; i < 4; i++) acc2[j][i] = 0ull;

    const int KT = K / 8;

    {
        float4 fa = *reinterpret_cast<const float4*>(Aptr);
        float af[4] = {fa.x, fa.y, fa.z, fa.w};
#pragma unroll
        for (int c = 0; c < 4; c++) {
            sA2[0][acol + c][2 * arow]     = af[c];
            sA2[0][acol + c][2 * arow + 1] = af[c];
        }
        *reinterpret_cast<float4*>(&sB[0][brow][bcol]) =
            *reinterpret_cast<const float4*>(Bptr);
    }
    __syncthreads();

    int buf = 0;
    for (int kt = 0; kt < KT; kt++) {
        float4 fa, fb;
        const bool has_next = (kt + 1 < KT);
        if (has_next) {
            fa = *reinterpret_cast<const float4*>(Aptr + (size_t)(kt + 1) * 8);
            fb = *reinterpret_cast<const float4*>(Bptr + (size_t)(kt + 1) * 8 * N);
        }

#pragma unroll
        for (int kk = 0; kk < 8; kk++) {
            const ulonglong2* pa0 =
                reinterpret_cast<const ulonglong2*>(&sA2[buf][kk][8 * ty]);
            const ulonglong2* pa1 =
                reinterpret_cast<const ulonglong2*>(&sA2[buf][kk][128 + 8 * ty]);
            ulonglong2 a01 = pa0[0];
            ulonglong2 a23 = pa0[1];
            ulonglong2 a45 = pa1[0];
            ulonglong2 a67 = pa1[1];
            const ulonglong2* pb0 =
                reinterpret_cast<const ulonglong2*>(&sB[buf][kk][4 * tx]);
            const ulonglong2* pb1 =
                reinterpret_cast<const ulonglong2*>(&sB[buf][kk][64 + 4 * tx]);
            ulonglong2 bl0 = pb0[0];
            ulonglong2 bl1 = pb1[0];

            unsigned long long a2[8] = {a01.x, a01.y, a23.x, a23.y,
                                        a45.x, a45.y, a67.x, a67.y};
            unsigned long long b2[4] = {bl0.x, bl0.y, bl1.x, bl1.y};
#pragma unroll
            for (int j = 0; j < 8; j++)
#pragma unroll
                for (int i = 0; i < 4; i++)
                    FMA2(acc2[j][i], a2[j], b2[i]);
        }

        if (has_next) {
            const int nb = buf ^ 1;
            float af[4] = {fa.x, fa.y, fa.z, fa.w};
#pragma unroll
            for (int c = 0; c < 4; c++) {
                sA2[nb][acol + c][2 * arow]     = af[c];
                sA2[nb][acol + c][2 * arow + 1] = af[c];
            }
            *reinterpret_cast<float4*>(&sB[nb][brow][bcol]) = fb;
            __syncthreads();
            buf = nb;
        }
    }

    float4 bias0 = *reinterpret_cast<const float4*>(&bias[n0 + 4 * tx]);
    float4 bias1 = *reinterpret_cast<const float4*>(&bias[n0 + 64 + 4 * tx]);
#pragma unroll
    for (int j = 0; j < 8; j++) {
        const int r = m0 + ((j < 4) ? (4 * ty + j) : (64 + 4 * ty + (j - 4)));
        float x0, x1, x2, x3, y0, y1, y2, y3;
        UNPK(x0, x1, acc2[j][0]);
        UNPK(x2, x3, acc2[j][1]);
        UNPK(y0, y1, acc2[j][2]);
        UNPK(y2, y3, acc2[j][3]);
        float4 o0 = {x0 + bias0.x, x1 + bias0.y, x2 + bias0.z, x3 + bias0.w};
        float4 o1 = {y0 + bias1.x, y1 + bias1.y, y2 + bias1.z, y3 + bias1.w};
        float* crow = C + (size_t)r * N + n0;
        *reinterpret_cast<float4*>(&crow[4 * tx])      = o0;
        *reinterpret_cast<float4*>(&crow[64 + 4 * tx]) = o1;
    }
}

// ============================================================================
// Flash attention, fp32 with packed f32x2 FMAs. Q tile 128, K tile 64.
// 256 threads: rows r = ty+16j (j<8), cols/keys c = tx+16i (i<4).
// Reduction axes are paired (even/odd in one 64-bit accumulator):
//   S  = Q K^T : pair over dh   (sQ row-major dh-contig, sK key-major dh-contig)
//   O += P V   : pair over keys (sP row-major key-contig, sVt dh-major key-contig)
// All tiles padded to row stride 66 floats -> 8B-aligned, conflict-free LDS.64.
// smem (dynamic 101376B):
//   sQ  [128][66] @ 0        sK [64][66] @ 33792
//   sVt [64][66]  @ 50688    sP [128][66] @ 67584
// ============================================================================
#define QTILE 128
#define KTILE 64
#define FPAD  66
#define FLASH_SMEM_BYTES 101376

__global__ __launch_bounds__(256, 2)
void flash_attn_kernel(const float* __restrict__ q,
                       const float* __restrict__ k,
                       const float* __restrict__ v,
                       float* __restrict__ o)
{
    extern __shared__ __align__(16) char smem[];
    float* sQ  = reinterpret_cast<float*>(smem);            // [128][66]
    float* sK  = reinterpret_cast<float*>(smem + 33792);    // [64][66]
    float* sVt = reinterpret_cast<float*>(smem + 50688);    // [64][66] (dh-major)
    float* sP  = reinterpret_cast<float*>(smem + 67584);    // [128][66]

    const int t  = threadIdx.x;
    const int tx = t & 15;
    const int ty = t >> 4;
    const int b  = blockIdx.z;
    const int h  = blockIdx.y;
    const int q0 = blockIdx.x * QTILE;
    const size_t hoff = (size_t)h * DHEAD;

    // ---- load Q tile (128 x 64), pre-scaled, float2 stores ----
#pragma unroll
    for (int p = 0; p < 8; p++) {
        int u    = t + 256 * p;       // 0..2047
        int row  = u >> 4;            // 0..127
        int col4 = u & 15;
        float4 f = *reinterpret_cast<const float4*>(
            &q[((size_t)(b * SEQ + q0 + row)) * DIM + hoff + col4 * 4]);
        float2* dst = reinterpret_cast<float2*>(&sQ[row * FPAD + col4 * 4]);
        dst[0] = make_float2(f.x * SCALE, f.y * SCALE);
        dst[1] = make_float2(f.z * SCALE, f.w * SCALE);
    }

    float m_i[8], l_i[8];
    unsigned long long oa2[8][4];
#pragma unroll
    for (int j = 0; j < 8; j++) {
        m_i[j] = -INFINITY;
        l_i[j] = 0.0f;
#pragma unroll
        for (int i = 0; i < 4; i++) oa2[j][i] = 0ull;
    }

    for (int kt = 0; kt < SEQ / KTILE; kt++) {
        const int kb = kt * KTILE;
        __syncthreads();   // prev tile's S/PV reads done before overwrite

        // ---- load K (key-major) and V (transposed dh-major) ----
#pragma unroll
        for (int p = 0; p < 4; p++) {
            int u    = t + 256 * p;   // 0..1023
            int row  = u >> 4;        // key 0..63
            int col4 = u & 15;
            size_t g = ((size_t)(b * SEQ + kb + row)) * DIM + hoff + col4 * 4;
            float4 fk = *reinterpret_cast<const float4*>(&k[g]);
            float2* kd = reinterpret_cast<float2*>(&sK[row * FPAD + col4 * 4]);
            kd[0] = make_float2(fk.x, fk.y);
            kd[1] = make_float2(fk.z, fk.w);
            float4 fv = *reinterpret_cast<const float4*>(&v[g]);
            sVt[(col4 * 4 + 0) * FPAD + row] = fv.x;
            sVt[(col4 * 4 + 1) * FPAD + row] = fv.y;
            sVt[(col4 * 4 + 2) * FPAD + row] = fv.z;
            sVt[(col4 * 4 + 3) * FPAD + row] = fv.w;
        }
        __syncthreads();

        // ---- S = Qs K^T (128 x 64), paired over dh ----
        unsigned long long s2[8][4];
#pragma unroll
        for (int j = 0; j < 8; j++)
#pragma unroll
            for (int i = 0; i < 4; i++) s2[j][i] = 0ull;

#pragma unroll 4
        for (int kk = 0; kk < DHEAD / 2; kk++) {
            unsigned long long qv2[8], kv2[4];
#pragma unroll
            for (int j = 0; j < 8; j++)
                qv2[j] = *reinterpret_cast<const unsigned long long*>(
                    &sQ[(ty + 16 * j) * FPAD + 2 * kk]);
#pragma unroll
            for (int i = 0; i < 4; i++)
                kv2[i] = *reinterpret_cast<const unsigned long long*>(
                    &sK[(tx + 16 * i) * FPAD + 2 * kk]);
#pragma unroll
            for (int j = 0; j < 8; j++)
#pragma unroll
                for (int i = 0; i < 4; i++)
                    FMA2(s2[j][i], qv2[j], kv2[i]);
        }

        // ---- online softmax (row reductions across 16 tx lanes) ----
#pragma unroll
        for (int j = 0; j < 8; j++) {
            float sv[4];
#pragma unroll
            for (int i = 0; i < 4; i++) {
                float lo, hi;
                UNPK(lo, hi, s2[j][i]);
                sv[i] = lo + hi;
            }
            float mx = fmaxf(fmaxf(sv[0], sv[1]), fmaxf(sv[2], sv[3]));
#pragma unroll
            for (int off = 8; off > 0; off >>= 1)
                mx = fmaxf(mx, __shfl_xor_sync(0xffffffffu, mx, off, 16));
            float mn = fmaxf(m_i[j], mx);
            float al = __expf(m_i[j] - mn);
            float rs = 0.0f;
#pragma unroll
            for (int i = 0; i < 4; i++) {
                sv[i] = __expf(sv[i] - mn);
                rs += sv[i];
            }
#pragma unroll
            for (int off = 8; off > 0; off >>= 1)
                rs += __shfl_xor_sync(0xffffffffu, rs, off, 16);
            l_i[j] = l_i[j] * al + rs;
            m_i[j] = mn;
            unsigned long long al2;
            PACK(al2, al, al);
#pragma unroll
            for (int i = 0; i < 4; i++) MUL2(oa2[j][i], al2);
#pragma unroll
            for (int i = 0; i < 4; i++)
                sP[(ty + 16 * j) * FPAD + tx + 16 * i] = sv[i];
        }
        __syncthreads();

        // ---- O += P @ V, paired over keys ----
#pragma unroll 4
        for (int jj = 0; jj < KTILE / 2; jj++) {
            unsigned long long pv2[8], vv2[4];
#pragma unroll
            for (int j = 0; j < 8; j++)
                pv2[j] = *reinterpret_cast<const unsigned long long*>(
                    &sP[(ty + 16 * j) * FPAD + 2 * jj]);
#pragma unroll
            for (int i = 0; i < 4; i++)
                vv2[i] = *reinterpret_cast<const unsigned long long*>(
                    &sVt[(tx + 16 * i) * FPAD + 2 * jj]);
#pragma unroll
            for (int j = 0; j < 8; j++)
#pragma unroll
                for (int i = 0; i < 4; i++)
                    FMA2(oa2[j][i], pv2[j], vv2[i]);
        }
    }

    // ---- normalize + write ----
#pragma unroll
    for (int j = 0; j < 8; j++) {
        float inv = 1.0f / l_i[j];
        const size_t row = (size_t)(b * SEQ + q0 + ty + 16 * j);
#pragma unroll
        for (int i = 0; i < 4; i++) {
            float lo, hi;
            UNPK(lo, hi, oa2[j][i]);
            o[row * DIM + hoff + tx + 16 * i] = (lo + hi) * inv;
        }
    }
}

// ============================================================================
// launch
// ============================================================================
extern "C" void kernel_launch(void* const* d_in, const int* in_sizes, int n_in,
                              void* d_out, int out_size)
{
    const float* x  = (const float*)d_in[0];
    const float* Wq = (const float*)d_in[1];
    const float* bq = (const float*)d_in[2];
    const float* Wl = (const float*)d_in[3];
    const float* bl = (const float*)d_in[4];
    const float* Wk = (const float*)d_in[5];
    const float* bk = (const float*)d_in[6];
    const float* Wv = (const float*)d_in[7];
    const float* bv = (const float*)d_in[8];
    const float* Wo = (const float*)d_in[9];
    const float* bo = (const float*)d_in[10];
    float* out = (float*)d_out;

    float *pq, *plat, *pk, *pv, *pao;
    cudaGetSymbolAddress((void**)&pq,   g_q);
    cudaGetSymbolAddress((void**)&plat, g_lat);
    cudaGetSymbolAddress((void**)&pk,   g_k);
    cudaGetSymbolAddress((void**)&pv,   g_v);
    cudaGetSymbolAddress((void**)&pao,  g_ao);

    cudaFuncSetAttribute(flash_attn_kernel,
                         cudaFuncAttributeMaxDynamicSharedMemorySize,
                         FLASH_SMEM_BYTES);

    dim3 thr(256);

    // q = x @ Wq + bq
    gemm_bias_kernel<<<dim3(DIM / 128, MROWS / 128), thr>>>(x, Wq, bq, pq, MROWS, DIM, DIM);
    // latent = x @ Wl + bl
    gemm_bias_kernel<<<dim3(LATENT / 128, MROWS / 128), thr>>>(x, Wl, bl, plat, MROWS, LATENT, DIM);
    // k = latent @ Wk + bk
    gemm_bias_kernel<<<dim3(DIM / 128, MROWS / 128), thr>>>(plat, Wk, bk, pk, MROWS, DIM, LATENT);
    // v = latent @ Wv + bv
    gemm_bias_kernel<<<dim3(DIM / 128, MROWS / 128), thr>>>(plat, Wv, bv, pv, MROWS, DIM, LATENT);

    // attention -> g_ao
    flash_attn_kernel<<<dim3(SEQ / QTILE, HEADS, BATCH), thr, FLASH_SMEM_BYTES>>>(pq, pk, pv, pao);

    // out = ao @ Wo + bo
    gemm_bias_kernel<<<dim3(DIM / 128, MROWS / 128), thr>>>(pao, Wo, bo, out, MROWS, DIM, DIM);
}

// round 12
// speedup vs baseline: 1.1077x; 1.1077x over previous
#include <cuda_runtime.h>
#include <math.h>

// ---------------- problem constants ----------------
#define BATCH   2
#define SEQ     2048
#define DIM     1024
#define HEADS   16
#define DHEAD   64
#define LATENT  256
#define MROWS   (BATCH * SEQ)          // 4096
#define SCALE   0.125f                 // DHEAD^-0.5

// ---------------- scratch (device globals; no allocation APIs) ----------------
__device__ float g_q  [MROWS * DIM];     // 16 MB
__device__ float g_lat[MROWS * LATENT];  //  4 MB
__device__ float g_k  [MROWS * DIM];     // 16 MB
__device__ float g_v  [MROWS * DIM];     // 16 MB
__device__ float g_ao [MROWS * DIM];     // 16 MB

// packed fp32x2 ops (Blackwell)
#define FMA2(acc, a, b) \
    asm("fma.rn.f32x2 %0, %1, %2, %0;" : "+l"(acc) : "l"(a), "l"(b))
#define MUL2(acc, s) \
    asm("mul.rn.f32x2 %0, %0, %1;" : "+l"(acc) : "l"(s))
#define UNPK(lo, hi, v) \
    asm("mov.b64 {%0, %1}, %2;" : "=f"(lo), "=f"(hi) : "l"(v))
#define PACK(v, lo, hi) \
    asm("mov.b64 %0, {%1, %2};" : "=l"(v) : "f"(lo), "f"(hi))

// ============================================================================
// SGEMM + bias via fma.rn.f32x2:  C[M,N] = A[M,K] @ B[K,N] + bias[N]
// 128x128 tile, BK=8, double-buffered, 256 threads, 8x8 microtile.
// A tile stored DUPLICATED in smem so ulonglong2 LDS yields {a,a} pairs.
// (measured: ~148 TF/s fp32 effective on Q-proj; regs=128, no spills)
// ============================================================================
__global__ __launch_bounds__(256, 2)
void gemm_bias_kernel(const float* __restrict__ A,
                      const float* __restrict__ B,
                      const float* __restrict__ bias,
                      float* __restrict__ C,
                      int M, int N, int K)
{
    __shared__ __align__(16) float sA2[2][8][260];
    __shared__ __align__(16) float sB [2][8][128];

    const int t  = threadIdx.x;
    const int tx = t & 15;
    const int ty = t >> 4;
    const int m0 = blockIdx.y * 128;
    const int n0 = blockIdx.x * 128;

    const int arow = t >> 1;
    const int acol = (t & 1) * 4;
    const int brow = t >> 5;
    const int bcol = (t & 31) * 4;

    const float* Aptr = A + (size_t)(m0 + arow) * K + acol;
    const float* Bptr = B + (size_t)brow * N + n0 + bcol;

    unsigned long long acc2[8][4];
#pragma unroll
    for (int j = 0; j < 8; j++)
#pragma unroll
        for (int i = 0; i < 4; i++) acc2[j][i] = 0ull;

    const int KT = K / 8;

    {
        float4 fa = *reinterpret_cast<const float4*>(Aptr);
        float af[4] = {fa.x, fa.y, fa.z, fa.w};
#pragma unroll
        for (int c = 0; c < 4; c++) {
            sA2[0][acol + c][2 * arow]     = af[c];
            sA2[0][acol + c][2 * arow + 1] = af[c];
        }
        *reinterpret_cast<float4*>(&sB[0][brow][bcol]) =
            *reinterpret_cast<const float4*>(Bptr);
    }
    __syncthreads();

    int buf = 0;
    for (int kt = 0; kt < KT; kt++) {
        float4 fa, fb;
        const bool has_next = (kt + 1 < KT);
        if (has_next) {
            fa = *reinterpret_cast<const float4*>(Aptr + (size_t)(kt + 1) * 8);
            fb = *reinterpret_cast<const float4*>(Bptr + (size_t)(kt + 1) * 8 * N);
        }

#pragma unroll
        for (int kk = 0; kk < 8; kk++) {
            const ulonglong2* pa0 =
                reinterpret_cast<const ulonglong2*>(&sA2[buf][kk][8 * ty]);
            const ulonglong2* pa1 =
                reinterpret_cast<const ulonglong2*>(&sA2[buf][kk][128 + 8 * ty]);
            ulonglong2 a01 = pa0[0];
            ulonglong2 a23 = pa0[1];
            ulonglong2 a45 = pa1[0];
            ulonglong2 a67 = pa1[1];
            const ulonglong2* pb0 =
                reinterpret_cast<const ulonglong2*>(&sB[buf][kk][4 * tx]);
            const ulonglong2* pb1 =
                reinterpret_cast<const ulonglong2*>(&sB[buf][kk][64 + 4 * tx]);
            ulonglong2 bl0 = pb0[0];
            ulonglong2 bl1 = pb1[0];

            unsigned long long a2[8] = {a01.x, a01.y, a23.x, a23.y,
                                        a45.x, a45.y, a67.x, a67.y};
            unsigned long long b2[4] = {bl0.x, bl0.y, bl1.x, bl1.y};
#pragma unroll
            for (int j = 0; j < 8; j++)
#pragma unroll
                for (int i = 0; i < 4; i++)
                    FMA2(acc2[j][i], a2[j], b2[i]);
        }

        if (has_next) {
            const int nb = buf ^ 1;
            float af[4] = {fa.x, fa.y, fa.z, fa.w};
#pragma unroll
            for (int c = 0; c < 4; c++) {
                sA2[nb][acol + c][2 * arow]     = af[c];
                sA2[nb][acol + c][2 * arow + 1] = af[c];
            }
            *reinterpret_cast<float4*>(&sB[nb][brow][bcol]) = fb;
            __syncthreads();
            buf = nb;
        }
    }

    float4 bias0 = *reinterpret_cast<const float4*>(&bias[n0 + 4 * tx]);
    float4 bias1 = *reinterpret_cast<const float4*>(&bias[n0 + 64 + 4 * tx]);
#pragma unroll
    for (int j = 0; j < 8; j++) {
        const int r = m0 + ((j < 4) ? (4 * ty + j) : (64 + 4 * ty + (j - 4)));
        float x0, x1, x2, x3, y0, y1, y2, y3;
        UNPK(x0, x1, acc2[j][0]);
        UNPK(x2, x3, acc2[j][1]);
        UNPK(y0, y1, acc2[j][2]);
        UNPK(y2, y3, acc2[j][3]);
        float4 o0 = {x0 + bias0.x, x1 + bias0.y, x2 + bias0.z, x3 + bias0.w};
        float4 o1 = {y0 + bias1.x, y1 + bias1.y, y2 + bias1.z, y3 + bias1.w};
        float* crow = C + (size_t)r * N + n0;
        *reinterpret_cast<float4*>(&crow[4 * tx])      = o0;
        *reinterpret_cast<float4*>(&crow[64 + 4 * tx]) = o1;
    }
}

// ============================================================================
// Flash attention, fp32 with packed f32x2 FMAs. Q tile 128, K tile 64.
// *** __launch_bounds__(256, 1): packed accumulators (s2 + oa2 = 128 regs)
// *** exceeded the 128-reg cap at minBlocks=2 and spilled (R11 regression
// *** 1677 -> 1822 us). At minBlocks=1 ptxas gets 255 regs -> no spills.
// 256 threads: rows r = ty+16j (j<8), cols/keys c = tx+16i (i<4).
// Reduction axes are paired (even/odd in one 64-bit accumulator):
//   S  = Q K^T : pair over dh   (sQ row-major dh-contig, sK key-major dh-contig)
//   O += P V   : pair over keys (sP row-major key-contig, sVt dh-major key-contig)
// All tiles padded to row stride 66 floats -> 8B-aligned, conflict-free LDS.64.
// smem (dynamic 101376B):
//   sQ  [128][66] @ 0        sK [64][66] @ 33792
//   sVt [64][66]  @ 50688    sP [128][66] @ 67584
// ============================================================================
#define QTILE 128
#define KTILE 64
#define FPAD  66
#define FLASH_SMEM_BYTES 101376

__global__ __launch_bounds__(256, 1)
void flash_attn_kernel(const float* __restrict__ q,
                       const float* __restrict__ k,
                       const float* __restrict__ v,
                       float* __restrict__ o)
{
    extern __shared__ __align__(16) char smem[];
    float* sQ  = reinterpret_cast<float*>(smem);            // [128][66]
    float* sK  = reinterpret_cast<float*>(smem + 33792);    // [64][66]
    float* sVt = reinterpret_cast<float*>(smem + 50688);    // [64][66] (dh-major)
    float* sP  = reinterpret_cast<float*>(smem + 67584);    // [128][66]

    const int t  = threadIdx.x;
    const int tx = t & 15;
    const int ty = t >> 4;
    const int b  = blockIdx.z;
    const int h  = blockIdx.y;
    const int q0 = blockIdx.x * QTILE;
    const size_t hoff = (size_t)h * DHEAD;

    // ---- load Q tile (128 x 64), pre-scaled, float2 stores ----
#pragma unroll
    for (int p = 0; p < 8; p++) {
        int u    = t + 256 * p;       // 0..2047
        int row  = u >> 4;            // 0..127
        int col4 = u & 15;
        float4 f = *reinterpret_cast<const float4*>(
            &q[((size_t)(b * SEQ + q0 + row)) * DIM + hoff + col4 * 4]);
        float2* dst = reinterpret_cast<float2*>(&sQ[row * FPAD + col4 * 4]);
        dst[0] = make_float2(f.x * SCALE, f.y * SCALE);
        dst[1] = make_float2(f.z * SCALE, f.w * SCALE);
    }

    float m_i[8], l_i[8];
    unsigned long long oa2[8][4];
#pragma unroll
    for (int j = 0; j < 8; j++) {
        m_i[j] = -INFINITY;
        l_i[j] = 0.0f;
#pragma unroll
        for (int i = 0; i < 4; i++) oa2[j][i] = 0ull;
    }

    for (int kt = 0; kt < SEQ / KTILE; kt++) {
        const int kb = kt * KTILE;
        __syncthreads();   // prev tile's S/PV reads done before overwrite

        // ---- load K (key-major) and V (transposed dh-major) ----
#pragma unroll
        for (int p = 0; p < 4; p++) {
            int u    = t + 256 * p;   // 0..1023
            int row  = u >> 4;        // key 0..63
            int col4 = u & 15;
            size_t g = ((size_t)(b * SEQ + kb + row)) * DIM + hoff + col4 * 4;
            float4 fk = *reinterpret_cast<const float4*>(&k[g]);
            float2* kd = reinterpret_cast<float2*>(&sK[row * FPAD + col4 * 4]);
            kd[0] = make_float2(fk.x, fk.y);
            kd[1] = make_float2(fk.z, fk.w);
            float4 fv = *reinterpret_cast<const float4*>(&v[g]);
            sVt[(col4 * 4 + 0) * FPAD + row] = fv.x;
            sVt[(col4 * 4 + 1) * FPAD + row] = fv.y;
            sVt[(col4 * 4 + 2) * FPAD + row] = fv.z;
            sVt[(col4 * 4 + 3) * FPAD + row] = fv.w;
        }
        __syncthreads();

        // ---- S = Qs K^T (128 x 64), paired over dh ----
        unsigned long long s2[8][4];
#pragma unroll
        for (int j = 0; j < 8; j++)
#pragma unroll
            for (int i = 0; i < 4; i++) s2[j][i] = 0ull;

#pragma unroll 4
        for (int kk = 0; kk < DHEAD / 2; kk++) {
            unsigned long long qv2[8], kv2[4];
#pragma unroll
            for (int j = 0; j < 8; j++)
                qv2[j] = *reinterpret_cast<const unsigned long long*>(
                    &sQ[(ty + 16 * j) * FPAD + 2 * kk]);
#pragma unroll
            for (int i = 0; i < 4; i++)
                kv2[i] = *reinterpret_cast<const unsigned long long*>(
                    &sK[(tx + 16 * i) * FPAD + 2 * kk]);
#pragma unroll
            for (int j = 0; j < 8; j++)
#pragma unroll
                for (int i = 0; i < 4; i++)
                    FMA2(s2[j][i], qv2[j], kv2[i]);
        }

        // ---- online softmax (row reductions across 16 tx lanes) ----
#pragma unroll
        for (int j = 0; j < 8; j++) {
            float sv[4];
#pragma unroll
            for (int i = 0; i < 4; i++) {
                float lo, hi;
                UNPK(lo, hi, s2[j][i]);
                sv[i] = lo + hi;
            }
            float mx = fmaxf(fmaxf(sv[0], sv[1]), fmaxf(sv[2], sv[3]));
#pragma unroll
            for (int off = 8; off > 0; off >>= 1)
                mx = fmaxf(mx, __shfl_xor_sync(0xffffffffu, mx, off, 16));
            float mn = fmaxf(m_i[j], mx);
            float al = __expf(m_i[j] - mn);
            float rs = 0.0f;
#pragma unroll
            for (int i = 0; i < 4; i++) {
                sv[i] = __expf(sv[i] - mn);
                rs += sv[i];
            }
#pragma unroll
            for (int off = 8; off > 0; off >>= 1)
                rs += __shfl_xor_sync(0xffffffffu, rs, off, 16);
            l_i[j] = l_i[j] * al + rs;
            m_i[j] = mn;
            unsigned long long al2;
            PACK(al2, al, al);
#pragma unroll
            for (int i = 0; i < 4; i++) MUL2(oa2[j][i], al2);
#pragma unroll
            for (int i = 0; i < 4; i++)
                sP[(ty + 16 * j) * FPAD + tx + 16 * i] = sv[i];
        }
        __syncthreads();

        // ---- O += P @ V, paired over keys ----
#pragma unroll 4
        for (int jj = 0; jj < KTILE / 2; jj++) {
            unsigned long long pv2[8], vv2[4];
#pragma unroll
            for (int j = 0; j < 8; j++)
                pv2[j] = *reinterpret_cast<const unsigned long long*>(
                    &sP[(ty + 16 * j) * FPAD + 2 * jj]);
#pragma unroll
            for (int i = 0; i < 4; i++)
                vv2[i] = *reinterpret_cast<const unsigned long long*>(
                    &sVt[(tx + 16 * i) * FPAD + 2 * jj]);
#pragma unroll
            for (int j = 0; j < 8; j++)
#pragma unroll
                for (int i = 0; i < 4; i++)
                    FMA2(oa2[j][i], pv2[j], vv2[i]);
        }
    }

    // ---- normalize + write ----
#pragma unroll
    for (int j = 0; j < 8; j++) {
        float inv = 1.0f / l_i[j];
        const size_t row = (size_t)(b * SEQ + q0 + ty + 16 * j);
#pragma unroll
        for (int i = 0; i < 4; i++) {
            float lo, hi;
            UNPK(lo, hi, oa2[j][i]);
            o[row * DIM + hoff + tx + 16 * i] = (lo + hi) * inv;
        }
    }
}

// ============================================================================
// launch
// ============================================================================
extern "C" void kernel_launch(void* const* d_in, const int* in_sizes, int n_in,
                              void* d_out, int out_size)
{
    const float* x  = (const float*)d_in[0];
    const float* Wq = (const float*)d_in[1];
    const float* bq = (const float*)d_in[2];
    const float* Wl = (const float*)d_in[3];
    const float* bl = (const float*)d_in[4];
    const float* Wk = (const float*)d_in[5];
    const float* bk = (const float*)d_in[6];
    const float* Wv = (const float*)d_in[7];
    const float* bv = (const float*)d_in[8];
    const float* Wo = (const float*)d_in[9];
    const float* bo = (const float*)d_in[10];
    float* out = (float*)d_out;

    float *pq, *plat, *pk, *pv, *pao;
    cudaGetSymbolAddress((void**)&pq,   g_q);
    cudaGetSymbolAddress((void**)&plat, g_lat);
    cudaGetSymbolAddress((void**)&pk,   g_k);
    cudaGetSymbolAddress((void**)&pv,   g_v);
    cudaGetSymbolAddress((void**)&pao,  g_ao);

    cudaFuncSetAttribute(flash_attn_kernel,
                         cudaFuncAttributeMaxDynamicSharedMemorySize,
                         FLASH_SMEM_BYTES);

    dim3 thr(256);

    // q = x @ Wq + bq
    gemm_bias_kernel<<<dim3(DIM / 128, MROWS / 128), thr>>>(x, Wq, bq, pq, MROWS, DIM, DIM);
    // latent = x @ Wl + bl
    gemm_bias_kernel<<<dim3(LATENT / 128, MROWS / 128), thr>>>(x, Wl, bl, plat, MROWS, LATENT, DIM);
    // k = latent @ Wk + bk
    gemm_bias_kernel<<<dim3(DIM / 128, MROWS / 128), thr>>>(plat, Wk, bk, pk, MROWS, DIM, LATENT);
    // v = latent @ Wv + bv
    gemm_bias_kernel<<<dim3(DIM / 128, MROWS / 128), thr>>>(plat, Wv, bv, pv, MROWS, DIM, LATENT);

    // attention -> g_ao
    flash_attn_kernel<<<dim3(SEQ / QTILE, HEADS, BATCH), thr, FLASH_SMEM_BYTES>>>(pq, pk, pv, pao);

    // out = ao @ Wo + bo
    gemm_bias_kernel<<<dim3(DIM / 128, MROWS / 128), thr>>>(pao, Wo, bo, out, MROWS, DIM, DIM);
}